// round 4
// baseline (speedup 1.0000x reference)
#include <cuda_runtime.h>
#include <cuda_bf16.h>
#include <cstdint>

// Problem constants
#define B_   256
#define T_   512
#define I_   256
#define H_   128
#define O_   1000
#define M_   (B_ * T_)      // 131072 rows of the input GEMM

// ---------------------------------------------------------------------------
// Scratch (static __device__ arrays: allocation-guard safe)
// ---------------------------------------------------------------------------
__device__ float g_xp[(size_t)M_ * H_];   // 64 MB
__device__ float g_h[B_ * H_];            // final hidden state

// ---------------------------------------------------------------------------
// Packed f32x2 helpers
// ---------------------------------------------------------------------------
__device__ __forceinline__ void fma2(unsigned long long& d,
                                     unsigned long long a,
                                     unsigned long long b) {
    asm("fma.rn.f32x2 %0, %1, %2, %0;" : "+l"(d) : "l"(a), "l"(b));
}
__device__ __forceinline__ float2 unpack2(unsigned long long v) {
    float2 f;
    asm("mov.b64 {%0, %1}, %2;" : "=f"(f.x), "=f"(f.y) : "l"(v));
    return f;
}

// Fast tanh: 1 - 2/(exp2(2x*log2e)+1), ~2e-7 abs error, correct saturation.
__device__ __forceinline__ float fast_tanh(float x) {
    float e;
    asm("ex2.approx.f32 %0, %1;" : "=f"(e) : "f"(x * 2.8853900817779268f));
    float r;
    asm("rcp.approx.f32 %0, %1;" : "=f"(r) : "f"(e + 1.0f));
    return 1.0f - 2.0f * r;
}

__device__ __forceinline__ uint32_t smem_u32(const void* p) {
    uint32_t a;
    asm("{ .reg .u64 t; cvta.to.shared.u64 t, %1; cvt.u32.u64 %0, t; }"
        : "=r"(a) : "l"(p));
    return a;
}
__device__ __forceinline__ uint32_t swz(uint32_t o) {     // 128B-row swizzle
    return o ^ ((o >> 3) & 0x70);
}
__device__ __forceinline__ void ldmx4(uint32_t* r, uint32_t addr) {
    asm volatile("ldmatrix.sync.aligned.m8n8.x4.shared.b16 {%0,%1,%2,%3}, [%4];"
                 : "=r"(r[0]), "=r"(r[1]), "=r"(r[2]), "=r"(r[3]) : "r"(addr));
}
__device__ __forceinline__ void mma16816(float* c, const uint32_t* a,
                                         uint32_t b0, uint32_t b1) {
    asm volatile(
        "mma.sync.aligned.m16n8k16.row.col.f32.bf16.bf16.f32 "
        "{%0,%1,%2,%3}, {%4,%5,%6,%7}, {%8,%9}, {%0,%1,%2,%3};"
        : "+f"(c[0]), "+f"(c[1]), "+f"(c[2]), "+f"(c[3])
        : "r"(a[0]), "r"(a[1]), "r"(a[2]), "r"(a[3]), "r"(b0), "r"(b1));
}

// ---------------------------------------------------------------------------
// Kernel 1 (HMMA): xp = x @ W_ih^T + (b_ih + b_hh)
// CTA: 128x128 tile, 256 thr (8 warps: 4m x 2n), K in 4 chunks of 64.
// fp32 -> bf16 hi/lo split, 3 mma passes, fp32 register accumulators.
// SMEM tiles 128 rows x 64 bf16 cols (128B rows), XOR-swizzled for ldmatrix.
// ---------------------------------------------------------------------------
#define BK_       64
#define SM_AHI    1024
#define SM_ALO    (SM_AHI + 16384)
#define SM_BHI    (SM_ALO + 16384)
#define SM_BLO    (SM_BHI + 16384)
#define SM_TOTAL  (SM_BLO + 16384)

__device__ __forceinline__ void split_store_f4(char* smem, uint32_t sw, float4 v,
                                               int hi_off, int lo_off) {
    __nv_bfloat162 h0 = __floats2bfloat162_rn(v.x, v.y);
    __nv_bfloat162 h1 = __floats2bfloat162_rn(v.z, v.w);
    float2 f0 = __bfloat1622float2(h0);
    float2 f1 = __bfloat1622float2(h1);
    __nv_bfloat162 l0 = __floats2bfloat162_rn(v.x - f0.x, v.y - f0.y);
    __nv_bfloat162 l1 = __floats2bfloat162_rn(v.z - f1.x, v.w - f1.y);
    uint2 hw, lw;
    hw.x = *(uint32_t*)&h0; hw.y = *(uint32_t*)&h1;
    lw.x = *(uint32_t*)&l0; lw.y = *(uint32_t*)&l1;
    *(uint2*)(smem + hi_off + sw) = hw;
    *(uint2*)(smem + lo_off + sw) = lw;
}

__global__ void __launch_bounds__(256) xp_gemm_tc(
    const float* __restrict__ X,      // [M_, I_]
    const float* __restrict__ Wih,    // [H_, I_]
    const float* __restrict__ b_ih,   // [H_]
    const float* __restrict__ b_hh)   // [H_]
{
    extern __shared__ char smem[];
    const uint32_t sb = smem_u32(smem);
    const int tid  = threadIdx.x;
    const int wid  = tid >> 5;
    const int lane = tid & 31;
    const int warp_m = wid & 3;        // 0..3 -> rows 32*warp_m
    const int warp_n = wid >> 2;       // 0..1 -> cols 64*warp_n
    const long mBase = (long)blockIdx.x * 128;

    // bias into smem[0..512)
    if (tid < H_) ((float*)smem)[tid] = b_ih[tid] + b_hh[tid];

    float c[16][4];                    // [mt*8+nt][4]
#pragma unroll
    for (int i = 0; i < 16; i++)
#pragma unroll
        for (int k = 0; k < 4; k++) c[i][k] = 0.f;

    const int r   = tid >> 1;          // row this thread loads (0..127)
    const int seg = tid & 1;           // which 32-col half of the 64-col chunk
    const float* arow = X   + (mBase + r) * I_ + seg * 32;
    const float* brow = Wih + r * I_ + seg * 32;

    // ldmatrix lane address components (computed once)
    const int amat = lane >> 3;
    const int a_r  = (amat & 1) * 8 + (lane & 7);     // A: row within 16
    const int a_c  = (amat >> 1) * 8;                 // A: k within 16
    const int b_nr = (amat >> 1) * 8 + (lane & 7);    // B: n within 16
    const int b_kc = (amat & 1) * 8;                  // B: k within 16

    for (int ch = 0; ch < 4; ch++) {
        const int k0 = ch * BK_;
        __syncthreads();               // previous chunk's compute done
#pragma unroll
        for (int q = 0; q < 8; q++) {
            uint32_t off = (uint32_t)(r * 128 + (seg * 32 + q * 4) * 2);
            uint32_t sw  = swz(off);
            split_store_f4(smem, sw, *(const float4*)(arow + k0 + q * 4), SM_AHI, SM_ALO);
            split_store_f4(smem, sw, *(const float4*)(brow + k0 + q * 4), SM_BHI, SM_BLO);
        }
        __syncthreads();

#pragma unroll
        for (int ks = 0; ks < 4; ks++) {
            uint32_t ahi[2][4], alo[2][4];
#pragma unroll
            for (int mt = 0; mt < 2; mt++) {
                uint32_t off = (uint32_t)((warp_m * 32 + mt * 16 + a_r) * 128
                                          + (ks * 16 + a_c) * 2);
                uint32_t sw = swz(off);
                ldmx4(ahi[mt], sb + SM_AHI + sw);
                ldmx4(alo[mt], sb + SM_ALO + sw);
            }
            uint32_t bhi[4][4], blo[4][4];
#pragma unroll
            for (int bt = 0; bt < 4; bt++) {
                uint32_t off = (uint32_t)((warp_n * 64 + bt * 16 + b_nr) * 128
                                          + (ks * 16 + b_kc) * 2);
                uint32_t sw = swz(off);
                ldmx4(bhi[bt], sb + SM_BHI + sw);
                ldmx4(blo[bt], sb + SM_BLO + sw);
            }
#pragma unroll
            for (int mt = 0; mt < 2; mt++)
#pragma unroll
                for (int nt = 0; nt < 8; nt++) {
                    const int bt = nt >> 1, sub = nt & 1;
                    float* acc = c[mt * 8 + nt];
                    mma16816(acc, ahi[mt], bhi[bt][sub * 2], bhi[bt][sub * 2 + 1]);
                    mma16816(acc, ahi[mt], blo[bt][sub * 2], blo[bt][sub * 2 + 1]);
                    mma16816(acc, alo[mt], bhi[bt][sub * 2], bhi[bt][sub * 2 + 1]);
                }
        }
    }

    // epilogue: c-frag (g,tg) layout; add bias, store float2 pairs
    const int g  = lane >> 2;
    const int tg = lane & 3;
    const float* bias = (const float*)smem;
#pragma unroll
    for (int mt = 0; mt < 2; mt++)
#pragma unroll
        for (int nt = 0; nt < 8; nt++) {
            const float* acc = c[mt * 8 + nt];
            int col = warp_n * 64 + nt * 8 + tg * 2;
            float bx = bias[col], by = bias[col + 1];
            long row0 = mBase + warp_m * 32 + mt * 16 + g;
            *(float2*)&g_xp[row0 * H_ + col]       = make_float2(acc[0] + bx, acc[1] + by);
            *(float2*)&g_xp[(row0 + 8) * H_ + col] = make_float2(acc[2] + bx, acc[3] + by);
        }
}

// ---------------------------------------------------------------------------
// Kernel 2: sequential recurrence.
// 128 CTAs x 512 threads (4 warps/SMSP). CTA owns 2 batch rows.
// Each output j handled by a LANE PAIR: lane (j_local*2 + khalf); khalf
// splits k into halves of 64. 32 fma2 -> 16 fma2 per thread, shfl.bfly(1)
// combines the halves. Weights: 64 floats (32 f32x2 regs) per thread.
// ---------------------------------------------------------------------------
__global__ void __launch_bounds__(512) rnn_scan_kernel(
    const float* __restrict__ Whh)    // [H_, H_]
{
    const int tid   = threadIdx.x;
    const int half  = tid >> 8;                 // 0/1: batch row within CTA
    const int wloc  = (tid >> 5) & 7;           // warp within half
    const int lane  = tid & 31;
    const int j     = wloc * 16 + (lane >> 1);  // output index 0..127
    const int khalf = lane & 1;                 // which 64-k half
    const int b     = blockIdx.x * 2 + half;

    __shared__ float hs[2][2][H_];              // [buf][half][j]

    // W_hh[j][khalf*64 .. +63] -> 32 packed f32x2 registers
    unsigned long long w2[32];
    {
        const ulonglong2* wp = (const ulonglong2*)(Whh + j * H_ + khalf * 64);
#pragma unroll
        for (int q = 0; q < 16; q++) {
            ulonglong2 v = wp[q];
            w2[2 * q + 0] = v.x;
            w2[2 * q + 1] = v.y;
        }
    }

    if (khalf == 0 && wloc < 4) {               // any 128 threads per half
        hs[0][half][j] = 0.f;
    }
    if (tid < 256) { hs[0][0][tid & 127] = 0.f; hs[0][1][tid & 127] = 0.f; }
    __syncthreads();

    const float* xprow = g_xp + ((long)b * T_) * H_ + j;
    float xb0 = xprow[0];
    float xb1 = xprow[H_];
    float hn  = 0.f;
    int   cur = 0;

    for (int t = 0; t < T_; t++) {
        float xn2 = (t + 2 < T_) ? xprow[(size_t)(t + 2) * H_] : 0.f;

        unsigned long long acc0 = 0ull, acc1 = 0ull;
        const double2* hp = (const double2*)&hs[cur][half][khalf * 64];
#pragma unroll
        for (int k = 0; k < 16; k++) {
            double2 h2 = hp[k];                 // 4 h values
            fma2(acc0, __double_as_longlong(h2.x), w2[2 * k + 0]);
            fma2(acc1, __double_as_longlong(h2.y), w2[2 * k + 1]);
        }
        float2 s0 = unpack2(acc0);
        float2 s1 = unpack2(acc1);
        float part = (s0.x + s0.y) + (s1.x + s1.y);
        float other = __shfl_xor_sync(0xFFFFFFFFu, part, 1);
        hn = fast_tanh(xb0 + part + other);
        if (khalf == 0) hs[cur ^ 1][half][j] = hn;
        __syncthreads();

        xb0 = xb1;
        xb1 = xn2;
        cur ^= 1;
    }

    if (khalf == 0) g_h[b * H_ + j] = hn;
}

// ---------------------------------------------------------------------------
// Kernel 3: out = h_last @ W_fc^T + b_fc
// ---------------------------------------------------------------------------
__global__ void __launch_bounds__(256) fc_kernel(
    const float* __restrict__ Wfc,    // [O_, H_]
    const float* __restrict__ bfc,    // [O_]
    float* __restrict__ out)          // [B_, O_]
{
    __shared__ float Ws[64][129];
    __shared__ float Hs[32][128];

    const int tid = threadIdx.x;
    const int oc = blockIdx.x * 64;
    const int bc = blockIdx.y * 32;

    for (int idx = tid; idx < 64 * 128; idx += 256) {
        int rr = idx >> 7, cc = idx & 127;
        Ws[rr][cc] = (oc + rr < O_) ? Wfc[(oc + rr) * H_ + cc] : 0.f;
    }
    for (int idx = tid; idx < 32 * 128; idx += 256) {
        int rr = idx >> 7, cc = idx & 127;
        Hs[rr][cc] = g_h[(bc + rr) * H_ + cc];
    }
    __syncthreads();

    const int o_loc = tid & 63;
    const int bg    = tid >> 6;
    const int o     = oc + o_loc;
    const float bias = (o < O_) ? bfc[o] : 0.f;

    float accv[8];
#pragma unroll
    for (int bi = 0; bi < 8; bi++) accv[bi] = bias;

#pragma unroll 4
    for (int k = 0; k < H_; k++) {
        float wv = Ws[o_loc][k];
#pragma unroll
        for (int bi = 0; bi < 8; bi++)
            accv[bi] = fmaf(Hs[bg * 8 + bi][k], wv, accv[bi]);
    }

    if (o < O_) {
#pragma unroll
        for (int bi = 0; bi < 8; bi++)
            out[(long)(bc + bg * 8 + bi) * O_ + o] = accv[bi];
    }
}

// ---------------------------------------------------------------------------
// Launch
// ---------------------------------------------------------------------------
extern "C" void kernel_launch(void* const* d_in, const int* in_sizes, int n_in,
                              void* d_out, int out_size)
{
    const float* x    = (const float*)d_in[0];   // [256,512,256]
    const float* Wih  = (const float*)d_in[1];   // [128,256]
    const float* Whh  = (const float*)d_in[2];   // [128,128]
    const float* b_ih = (const float*)d_in[3];   // [128]
    const float* b_hh = (const float*)d_in[4];   // [128]
    const float* Wfc  = (const float*)d_in[5];   // [1000,128]
    const float* bfc  = (const float*)d_in[6];   // [1000]
    float* out = (float*)d_out;                  // [256,1000]

    static bool attr_set = false;
    if (!attr_set) {
        cudaFuncSetAttribute(xp_gemm_tc,
                             cudaFuncAttributeMaxDynamicSharedMemorySize, SM_TOTAL);
        attr_set = true;
    }

    xp_gemm_tc<<<M_ / 128, 256, SM_TOTAL>>>(x, Wih, b_ih, b_hh);
    rnn_scan_kernel<<<B_ / 2, 512>>>(Whh);
    fc_kernel<<<dim3((O_ + 63) / 64, B_ / 32), 256>>>(Wfc, bfc, out);
}

// round 5
// speedup vs baseline: 1.3853x; 1.3853x over previous
#include <cuda_runtime.h>
#include <cuda_bf16.h>
#include <cstdint>

// Problem constants
#define B_   256
#define T_   512
#define I_   256
#define H_   128
#define O_   1000
#define M_   (B_ * T_)      // 131072 rows of the input GEMM

// ---------------------------------------------------------------------------
// Scratch (static __device__ arrays: allocation-guard safe)
// ---------------------------------------------------------------------------
__device__ float g_xp[(size_t)M_ * H_];   // 64 MB
__device__ float g_h[B_ * H_];            // final hidden state

// ---------------------------------------------------------------------------
// Packed f32x2 helpers
// ---------------------------------------------------------------------------
__device__ __forceinline__ void fma2(unsigned long long& d,
                                     unsigned long long a,
                                     unsigned long long b) {
    asm("fma.rn.f32x2 %0, %1, %2, %0;" : "+l"(d) : "l"(a), "l"(b));
}
__device__ __forceinline__ float2 unpack2(unsigned long long v) {
    float2 f;
    asm("mov.b64 {%0, %1}, %2;" : "=f"(f.x), "=f"(f.y) : "l"(v));
    return f;
}

// Fast tanh: 1 - 2/(exp2(2x*log2e)+1), ~2e-7 abs error, correct saturation.
__device__ __forceinline__ float fast_tanh(float x) {
    float e;
    asm("ex2.approx.f32 %0, %1;" : "=f"(e) : "f"(x * 2.8853900817779268f));
    float r;
    asm("rcp.approx.f32 %0, %1;" : "=f"(r) : "f"(e + 1.0f));
    return 1.0f - 2.0f * r;
}

__device__ __forceinline__ uint32_t smem_u32(const void* p) {
    uint32_t a;
    asm("{ .reg .u64 t; cvta.to.shared.u64 t, %1; cvt.u32.u64 %0, t; }"
        : "=r"(a) : "l"(p));
    return a;
}
__device__ __forceinline__ uint32_t swz(uint32_t o) {     // 128B-row swizzle
    return o ^ ((o >> 3) & 0x70);
}
__device__ __forceinline__ void ldmx4(uint32_t* r, uint32_t addr) {
    asm volatile("ldmatrix.sync.aligned.m8n8.x4.shared.b16 {%0,%1,%2,%3}, [%4];"
                 : "=r"(r[0]), "=r"(r[1]), "=r"(r[2]), "=r"(r[3]) : "r"(addr));
}
__device__ __forceinline__ void mma16816(float* c, const uint32_t* a,
                                         uint32_t b0, uint32_t b1) {
    asm volatile(
        "mma.sync.aligned.m16n8k16.row.col.f32.bf16.bf16.f32 "
        "{%0,%1,%2,%3}, {%4,%5,%6,%7}, {%8,%9}, {%0,%1,%2,%3};"
        : "+f"(c[0]), "+f"(c[1]), "+f"(c[2]), "+f"(c[3])
        : "r"(a[0]), "r"(a[1]), "r"(a[2]), "r"(a[3]), "r"(b0), "r"(b1));
}

// ---------------------------------------------------------------------------
// Kernel 1 (HMMA, double-buffered): xp = x @ W_ih^T + (b_ih + b_hh)
// CTA: 128x128 tile, 256 thr (8 warps: 4m x 2n), K = 4 chunks of 64.
// fp32 -> bf16 hi/lo split, 3 mma passes, fp32 register accumulators.
// Two 64KB smem buffers; next chunk's loads/convert overlap current mma.
// ---------------------------------------------------------------------------
#define TILE_SZ   16384                  // one 128x64 bf16 tile
#define BUF_SZ    (4 * TILE_SZ)          // Ahi, Alo, Bhi, Blo
#define OFF_AHI   0
#define OFF_ALO   16384
#define OFF_BHI   32768
#define OFF_BLO   49152
#define SM_BUF0   1024
#define SM_BUF1   (1024 + BUF_SZ)
#define SM_TOTAL  (1024 + 2 * BUF_SZ)    // 132096 bytes

__device__ __forceinline__ void split_store_f4(char* buf, uint32_t sw, float4 v,
                                               int hi_off, int lo_off) {
    __nv_bfloat162 h0 = __floats2bfloat162_rn(v.x, v.y);
    __nv_bfloat162 h1 = __floats2bfloat162_rn(v.z, v.w);
    float2 f0 = __bfloat1622float2(h0);
    float2 f1 = __bfloat1622float2(h1);
    __nv_bfloat162 l0 = __floats2bfloat162_rn(v.x - f0.x, v.y - f0.y);
    __nv_bfloat162 l1 = __floats2bfloat162_rn(v.z - f1.x, v.w - f1.y);
    uint2 hw, lw;
    hw.x = *(uint32_t*)&h0; hw.y = *(uint32_t*)&h1;
    lw.x = *(uint32_t*)&l0; lw.y = *(uint32_t*)&l1;
    *(uint2*)(buf + hi_off + sw) = hw;
    *(uint2*)(buf + lo_off + sw) = lw;
}

__device__ __forceinline__ void mma_ks(uint32_t base_sb, int ks,
                                       int warp_m, int warp_n,
                                       int a_r, int a_c, int b_nr, int b_kc,
                                       float (*c)[4]) {
    uint32_t ahi[2][4], alo[2][4];
#pragma unroll
    for (int mt = 0; mt < 2; mt++) {
        uint32_t off = (uint32_t)((warp_m * 32 + mt * 16 + a_r) * 128
                                  + (ks * 16 + a_c) * 2);
        uint32_t sw = swz(off);
        ldmx4(ahi[mt], base_sb + OFF_AHI + sw);
        ldmx4(alo[mt], base_sb + OFF_ALO + sw);
    }
    uint32_t bhi[4][4], blo[4][4];
#pragma unroll
    for (int bt = 0; bt < 4; bt++) {
        uint32_t off = (uint32_t)((warp_n * 64 + bt * 16 + b_nr) * 128
                                  + (ks * 16 + b_kc) * 2);
        uint32_t sw = swz(off);
        ldmx4(bhi[bt], base_sb + OFF_BHI + sw);
        ldmx4(blo[bt], base_sb + OFF_BLO + sw);
    }
#pragma unroll
    for (int mt = 0; mt < 2; mt++)
#pragma unroll
        for (int nt = 0; nt < 8; nt++) {
            const int bt = nt >> 1, sub = nt & 1;
            float* acc = c[mt * 8 + nt];
            mma16816(acc, ahi[mt], bhi[bt][sub * 2], bhi[bt][sub * 2 + 1]);
            mma16816(acc, ahi[mt], blo[bt][sub * 2], blo[bt][sub * 2 + 1]);
            mma16816(acc, alo[mt], bhi[bt][sub * 2], bhi[bt][sub * 2 + 1]);
        }
}

__global__ void __launch_bounds__(256) xp_gemm_tc(
    const float* __restrict__ X,      // [M_, I_]
    const float* __restrict__ Wih,    // [H_, I_]
    const float* __restrict__ b_ih,   // [H_]
    const float* __restrict__ b_hh)   // [H_]
{
    extern __shared__ char smem[];
    const uint32_t sb = smem_u32(smem);
    const int tid  = threadIdx.x;
    const int wid  = tid >> 5;
    const int lane = tid & 31;
    const int warp_m = wid & 3;
    const int warp_n = wid >> 2;
    const long mBase = (long)blockIdx.x * 128;

    if (tid < H_) ((float*)smem)[tid] = b_ih[tid] + b_hh[tid];

    float c[16][4];
#pragma unroll
    for (int i = 0; i < 16; i++)
#pragma unroll
        for (int k = 0; k < 4; k++) c[i][k] = 0.f;

    const int r   = tid >> 1;
    const int seg = tid & 1;
    const float* arow = X   + (mBase + r) * I_ + seg * 32;
    const float* brow = Wih + r * I_ + seg * 32;

    const int amat = lane >> 3;
    const int a_r  = (amat & 1) * 8 + (lane & 7);
    const int a_c  = (amat >> 1) * 8;
    const int b_nr = (amat >> 1) * 8 + (lane & 7);
    const int b_kc = (amat & 1) * 8;

    // swizzled store offsets for this thread's 8 quads (same every chunk)
    uint32_t ssw[8];
#pragma unroll
    for (int q = 0; q < 8; q++)
        ssw[q] = swz((uint32_t)(r * 128 + (seg * 32 + q * 4) * 2));

    // prologue: chunk 0 into buf0
    {
        char* buf = smem + SM_BUF0;
#pragma unroll
        for (int q = 0; q < 8; q++) {
            split_store_f4(buf, ssw[q], *(const float4*)(arow + q * 4), OFF_AHI, OFF_ALO);
            split_store_f4(buf, ssw[q], *(const float4*)(brow + q * 4), OFF_BHI, OFF_BLO);
        }
    }
    __syncthreads();

    for (int ch = 0; ch < 4; ch++) {
        const uint32_t csb = sb + SM_BUF0 + (uint32_t)(ch & 1) * BUF_SZ;
        char* nxt = smem + SM_BUF0 + ((ch & 1) ^ 1) * BUF_SZ;
        const int k1 = (ch + 1) * 64;

        float4 a_ld[8];
        if (ch < 3) {
#pragma unroll
            for (int q = 0; q < 8; q++)
                a_ld[q] = *(const float4*)(arow + k1 + q * 4);
        }

        mma_ks(csb, 0, warp_m, warp_n, a_r, a_c, b_nr, b_kc, c);
        mma_ks(csb, 1, warp_m, warp_n, a_r, a_c, b_nr, b_kc, c);

        float4 b_ld[8];
        if (ch < 3) {
#pragma unroll
            for (int q = 0; q < 8; q++)
                split_store_f4(nxt, ssw[q], a_ld[q], OFF_AHI, OFF_ALO);
#pragma unroll
            for (int q = 0; q < 8; q++)
                b_ld[q] = *(const float4*)(brow + k1 + q * 4);
        }

        mma_ks(csb, 2, warp_m, warp_n, a_r, a_c, b_nr, b_kc, c);
        mma_ks(csb, 3, warp_m, warp_n, a_r, a_c, b_nr, b_kc, c);

        if (ch < 3) {
#pragma unroll
            for (int q = 0; q < 8; q++)
                split_store_f4(nxt, ssw[q], b_ld[q], OFF_BHI, OFF_BLO);
        }
        __syncthreads();
    }

    // epilogue
    const int g  = lane >> 2;
    const int tg = lane & 3;
    const float* bias = (const float*)smem;
#pragma unroll
    for (int mt = 0; mt < 2; mt++)
#pragma unroll
        for (int nt = 0; nt < 8; nt++) {
            const float* acc = c[mt * 8 + nt];
            int col = warp_n * 64 + nt * 8 + tg * 2;
            float bx = bias[col], by = bias[col + 1];
            long row0 = mBase + warp_m * 32 + mt * 16 + g;
            *(float2*)&g_xp[row0 * H_ + col]       = make_float2(acc[0] + bx, acc[1] + by);
            *(float2*)&g_xp[(row0 + 8) * H_ + col] = make_float2(acc[2] + bx, acc[3] + by);
        }
}

// ---------------------------------------------------------------------------
// Kernel 2: sequential recurrence (R2 structure + 4 accumulators + per-half
// named barriers). 128 CTAs x 256 threads, 2 batch rows per CTA, one thread
// per output j with the full 128-k dot product as packed f32x2 FMAs.
// ---------------------------------------------------------------------------
__global__ void __launch_bounds__(256) rnn_scan_kernel(
    const float* __restrict__ Whh)    // [H_, H_]
{
    const int tid  = threadIdx.x;
    const int half = tid >> 7;        // 0/1: batch row of this CTA
    const int j    = tid & 127;
    const int b    = blockIdx.x * 2 + half;
    const int barid = 1 + half;       // named barrier per half (128 thr each)

    __shared__ float hs[2][2][H_];    // [buf][half][j]

    // W_hh row j -> 64 packed f32x2 registers
    unsigned long long w2[64];
    const ulonglong2* wrow = (const ulonglong2*)(Whh + j * H_);
#pragma unroll
    for (int q = 0; q < 32; q++) {
        ulonglong2 v = wrow[q];
        w2[2 * q + 0] = v.x;
        w2[2 * q + 1] = v.y;
    }

    hs[0][half][j] = 0.f;
    __syncthreads();

    const float* xprow = g_xp + ((long)b * T_) * H_ + j;
    float xb0 = xprow[0];
    float xb1 = xprow[H_];
    float hn  = 0.f;
    int   cur = 0;

    for (int t = 0; t < T_; t++) {
        float xn2 = (t + 2 < T_) ? xprow[(size_t)(t + 2) * H_] : 0.f;

        unsigned long long a0 = 0ull, a1 = 0ull, a2 = 0ull, a3 = 0ull;
        const double2* hp = (const double2*)hs[cur][half];
#pragma unroll
        for (int k = 0; k < 16; k++) {
            double2 hA = hp[2 * k + 0];          // broadcast LDS.128
            double2 hB = hp[2 * k + 1];
            fma2(a0, __double_as_longlong(hA.x), w2[4 * k + 0]);
            fma2(a1, __double_as_longlong(hA.y), w2[4 * k + 1]);
            fma2(a2, __double_as_longlong(hB.x), w2[4 * k + 2]);
            fma2(a3, __double_as_longlong(hB.y), w2[4 * k + 3]);
        }
        float2 s0 = unpack2(a0), s1 = unpack2(a1);
        float2 s2 = unpack2(a2), s3 = unpack2(a3);
        float dot = ((s0.x + s0.y) + (s1.x + s1.y))
                  + ((s2.x + s2.y) + (s3.x + s3.y));
        hn = fast_tanh(xb0 + dot);
        hs[cur ^ 1][half][j] = hn;
        asm volatile("bar.sync %0, 128;" :: "r"(barid) : "memory");

        xb0 = xb1;
        xb1 = xn2;
        cur ^= 1;
    }

    g_h[b * H_ + j] = hn;
}

// ---------------------------------------------------------------------------
// Kernel 3: out = h_last @ W_fc^T + b_fc
// ---------------------------------------------------------------------------
__global__ void __launch_bounds__(256) fc_kernel(
    const float* __restrict__ Wfc,    // [O_, H_]
    const float* __restrict__ bfc,    // [O_]
    float* __restrict__ out)          // [B_, O_]
{
    __shared__ float Ws[64][129];
    __shared__ float Hs[32][128];

    const int tid = threadIdx.x;
    const int oc = blockIdx.x * 64;
    const int bc = blockIdx.y * 32;

    for (int idx = tid; idx < 64 * 128; idx += 256) {
        int rr = idx >> 7, cc = idx & 127;
        Ws[rr][cc] = (oc + rr < O_) ? Wfc[(oc + rr) * H_ + cc] : 0.f;
    }
    for (int idx = tid; idx < 32 * 128; idx += 256) {
        int rr = idx >> 7, cc = idx & 127;
        Hs[rr][cc] = g_h[(bc + rr) * H_ + cc];
    }
    __syncthreads();

    const int o_loc = tid & 63;
    const int bg    = tid >> 6;
    const int o     = oc + o_loc;
    const float bias = (o < O_) ? bfc[o] : 0.f;

    float accv[8];
#pragma unroll
    for (int bi = 0; bi < 8; bi++) accv[bi] = bias;

#pragma unroll 4
    for (int k = 0; k < H_; k++) {
        float wv = Ws[o_loc][k];
#pragma unroll
        for (int bi = 0; bi < 8; bi++)
            accv[bi] = fmaf(Hs[bg * 8 + bi][k], wv, accv[bi]);
    }

    if (o < O_) {
#pragma unroll
        for (int bi = 0; bi < 8; bi++)
            out[(long)(bc + bg * 8 + bi) * O_ + o] = accv[bi];
    }
}

// ---------------------------------------------------------------------------
// Launch
// ---------------------------------------------------------------------------
extern "C" void kernel_launch(void* const* d_in, const int* in_sizes, int n_in,
                              void* d_out, int out_size)
{
    const float* x    = (const float*)d_in[0];   // [256,512,256]
    const float* Wih  = (const float*)d_in[1];   // [128,256]
    const float* Whh  = (const float*)d_in[2];   // [128,128]
    const float* b_ih = (const float*)d_in[3];   // [128]
    const float* b_hh = (const float*)d_in[4];   // [128]
    const float* Wfc  = (const float*)d_in[5];   // [1000,128]
    const float* bfc  = (const float*)d_in[6];   // [1000]
    float* out = (float*)d_out;                  // [256,1000]

    static bool attr_set = false;
    if (!attr_set) {
        cudaFuncSetAttribute(xp_gemm_tc,
                             cudaFuncAttributeMaxDynamicSharedMemorySize, SM_TOTAL);
        attr_set = true;
    }

    xp_gemm_tc<<<M_ / 128, 256, SM_TOTAL>>>(x, Wih, b_ih, b_hh);
    rnn_scan_kernel<<<B_ / 2, 256>>>(Whh);
    fc_kernel<<<dim3((O_ + 63) / 64, B_ / 32), 256>>>(Wfc, bfc, out);
}

// round 6
// speedup vs baseline: 1.5401x; 1.1117x over previous
#include <cuda_runtime.h>
#include <cuda_bf16.h>
#include <cstdint>

// Problem constants
#define B_   256
#define T_   512
#define I_   256
#define H_   128
#define O_   1000
#define M_   (B_ * T_)

// ---------------------------------------------------------------------------
// Scratch (static __device__ arrays: allocation-guard safe)
// ---------------------------------------------------------------------------
__device__ float g_xp[(size_t)M_ * H_];   // 64 MB xp buffer (L2-resident working set)
__device__ float g_h[B_ * H_];            // final hidden state

// ---------------------------------------------------------------------------
// Packed f32x2 helpers
// ---------------------------------------------------------------------------
__device__ __forceinline__ void fma2(unsigned long long& d,
                                     unsigned long long a,
                                     unsigned long long b) {
    asm("fma.rn.f32x2 %0, %1, %2, %0;" : "+l"(d) : "l"(a), "l"(b));
}
__device__ __forceinline__ float2 unpack2(unsigned long long v) {
    float2 f;
    asm("mov.b64 {%0, %1}, %2;" : "=f"(f.x), "=f"(f.y) : "l"(v));
    return f;
}

// Fast tanh: 1 - 2/(exp2(2x*log2e)+1), ~2e-7 abs error, correct saturation.
__device__ __forceinline__ float fast_tanh(float x) {
    float e;
    asm("ex2.approx.f32 %0, %1;" : "=f"(e) : "f"(x * 2.8853900817779268f));
    float r;
    asm("rcp.approx.f32 %0, %1;" : "=f"(r) : "f"(e + 1.0f));
    return 1.0f - 2.0f * r;
}

__device__ __forceinline__ uint32_t smem_u32(const void* p) {
    uint32_t a;
    asm("{ .reg .u64 t; cvta.to.shared.u64 t, %1; cvt.u32.u64 %0, t; }"
        : "=r"(a) : "l"(p));
    return a;
}
__device__ __forceinline__ uint32_t swz(uint32_t o) {     // 128B-row swizzle
    return o ^ ((o >> 3) & 0x70);
}
__device__ __forceinline__ void ldmx4(uint32_t* r, uint32_t addr) {
    asm volatile("ldmatrix.sync.aligned.m8n8.x4.shared.b16 {%0,%1,%2,%3}, [%4];"
                 : "=r"(r[0]), "=r"(r[1]), "=r"(r[2]), "=r"(r[3]) : "r"(addr));
}
__device__ __forceinline__ void mma16816(float* c, const uint32_t* a,
                                         uint32_t b0, uint32_t b1) {
    asm volatile(
        "mma.sync.aligned.m16n8k16.row.col.f32.bf16.bf16.f32 "
        "{%0,%1,%2,%3}, {%4,%5,%6,%7}, {%8,%9}, {%0,%1,%2,%3};"
        : "+f"(c[0]), "+f"(c[1]), "+f"(c[2]), "+f"(c[3])
        : "r"(a[0]), "r"(a[1]), "r"(a[2]), "r"(a[3]), "r"(b0), "r"(b1));
}

__device__ __forceinline__ void split_store_f4(char* buf, uint32_t sw, float4 v,
                                               int hi_off, int lo_off) {
    __nv_bfloat162 h0 = __floats2bfloat162_rn(v.x, v.y);
    __nv_bfloat162 h1 = __floats2bfloat162_rn(v.z, v.w);
    float2 f0 = __bfloat1622float2(h0);
    float2 f1 = __bfloat1622float2(h1);
    __nv_bfloat162 l0 = __floats2bfloat162_rn(v.x - f0.x, v.y - f0.y);
    __nv_bfloat162 l1 = __floats2bfloat162_rn(v.z - f1.x, v.w - f1.y);
    uint2 hw, lw;
    hw.x = *(uint32_t*)&h0; hw.y = *(uint32_t*)&h1;
    lw.x = *(uint32_t*)&l0; lw.y = *(uint32_t*)&l1;
    *(uint2*)(buf + hi_off + sw) = hw;
    *(uint2*)(buf + lo_off + sw) = lw;
}

// ---------------------------------------------------------------------------
// SMEM layout (dynamic)
// ---------------------------------------------------------------------------
#define SM_BIAS   0          // float[128]                     (512 B)
#define SM_FLAGS  512        // int[16]: [row][ti] = row*8+ti  (64 B)
#define SM_HS     1024       // float[2][2][128]               (4 KB)
#define SM_B      8192       // W_ih bf16 hi/lo, 4 chunks x 32KB = 128 KB
#define SM_A      139264     // A tile 64x64 hi+lo = 16 KB
#define SM_TOTAL  155648

// ---------------------------------------------------------------------------
// Fused kernel: 128 CTAs x 384 threads.
//   threads [0,256):   recurrence for 2 batch rows (per-half, 1 thread per j)
//   threads [256,384): HMMA producers computing this CTA's xp tiles
// Producers signal per-(row,tile64) smem flags; consumers gate prefetches.
// ---------------------------------------------------------------------------
__global__ void __launch_bounds__(384, 1) fused_rnn(
    const float* __restrict__ X,      // [M_, I_]
    const float* __restrict__ Wih,    // [H_, I_]
    const float* __restrict__ Whh,    // [H_, H_]
    const float* __restrict__ b_ih,   // [H_]
    const float* __restrict__ b_hh)   // [H_]
{
    extern __shared__ char smem[];
    const uint32_t sb = smem_u32(smem);
    const int tid = threadIdx.x;

    float* bias = (float*)(smem + SM_BIAS);
    volatile int* flags = (volatile int*)(smem + SM_FLAGS);
    float (*hs)[2][H_] = (float (*)[2][H_])(smem + SM_HS);

    // ---- convergent prologue (single __syncthreads call site) ----
    if (tid < 16)  ((int*)(smem + SM_FLAGS))[tid] = 0;
    if (tid < H_)  bias[tid] = b_ih[tid] + b_hh[tid];
    if (tid < 256) hs[0][tid >> 7][tid & 127] = 0.f;
    if (tid >= 256) {
        // convert W_ih (128x256 fp32) into resident hi/lo bf16 smem tiles
        const int r = tid - 256;                 // row 0..127
        const float* brow = Wih + r * I_;
#pragma unroll
        for (int ch = 0; ch < 4; ch++) {
            char* btile = smem + SM_B + ch * 32768;
#pragma unroll
            for (int q = 0; q < 16; q++) {
                uint32_t off = (uint32_t)(r * 128 + q * 8);
                split_store_f4(btile, swz(off),
                               *(const float4*)(brow + ch * 64 + q * 4),
                               0, 16384);
            }
        }
    }
    __syncthreads();

    if (tid < 256) {
        // =================== CONSUMER: recurrence ===================
        const int half  = tid >> 7;
        const int j     = tid & 127;
        const int b     = blockIdx.x * 2 + half;
        const int barid = 1 + half;

        unsigned long long w2[64];
        const ulonglong2* wrow = (const ulonglong2*)(Whh + j * H_);
#pragma unroll
        for (int q = 0; q < 32; q++) {
            ulonglong2 v = wrow[q];
            w2[2 * q + 0] = v.x;
            w2[2 * q + 1] = v.y;
        }

        const float* xprow = g_xp + ((long)b * T_) * H_ + j;

        // wait for tile 0 of this row
        while (flags[half * 8 + 0] == 0) __nanosleep(64);
        __threadfence_block();

        float xb0 = xprow[0];
        float xb1 = xprow[H_];
        float hn  = 0.f;
        int   cur = 0;

        for (int t = 0; t < T_; t++) {
            const int tn = t + 2;
            float xn2 = 0.f;
            if (tn < T_) {
                if ((tn & 63) == 0) {              // crossing into next tile
                    while (flags[half * 8 + (tn >> 6)] == 0) __nanosleep(64);
                    __threadfence_block();
                }
                xn2 = xprow[(size_t)tn * H_];
            }

            unsigned long long a0 = 0ull, a1 = 0ull, a2 = 0ull, a3 = 0ull;
            const double2* hp = (const double2*)hs[cur][half];
#pragma unroll
            for (int k = 0; k < 16; k++) {
                double2 hA = hp[2 * k + 0];
                double2 hB = hp[2 * k + 1];
                fma2(a0, __double_as_longlong(hA.x), w2[4 * k + 0]);
                fma2(a1, __double_as_longlong(hA.y), w2[4 * k + 1]);
                fma2(a2, __double_as_longlong(hB.x), w2[4 * k + 2]);
                fma2(a3, __double_as_longlong(hB.y), w2[4 * k + 3]);
            }
            float2 s0 = unpack2(a0), s1 = unpack2(a1);
            float2 s2 = unpack2(a2), s3 = unpack2(a3);
            float dot = ((s0.x + s0.y) + (s1.x + s1.y))
                      + ((s2.x + s2.y) + (s3.x + s3.y));
            hn = fast_tanh(xb0 + dot);
            hs[cur ^ 1][half][j] = hn;
            asm volatile("bar.sync %0, 128;" :: "r"(barid) : "memory");

            xb0 = xb1;
            xb1 = xn2;
            cur ^= 1;
        }

        g_h[b * H_ + j] = hn;
    } else {
        // =================== PRODUCER: xp GEMM tiles ===================
        const int wg   = tid - 256;        // 0..127
        const int pw   = wg >> 5;          // warp 0..3
        const int lane = wg & 31;

        const int amat = lane >> 3;
        const int a_r  = (amat & 1) * 8 + (lane & 7);
        const int a_c  = (amat >> 1) * 8;
        const int b_nr = (amat >> 1) * 8 + (lane & 7);
        const int b_kc = (amat & 1) * 8;

        const int r2  = wg >> 1;           // A-load row 0..63
        const int seg = wg & 1;            // A-load 32-col half

        const int g_  = lane >> 2;
        const int tg  = lane & 3;

        for (int tile = 0; tile < 16; tile++) {
            const int row = tile & 1;      // which batch row of this CTA
            const int ti  = tile >> 1;     // 64-step tile index within row
            const long mb = ((long)(blockIdx.x * 2 + row)) * T_ + ti * 64;

            float acc[16][4];
#pragma unroll
            for (int i = 0; i < 16; i++)
#pragma unroll
                for (int k = 0; k < 4; k++) acc[i][k] = 0.f;

            const float* arow = X + (mb + r2) * I_ + seg * 32;

            for (int ch = 0; ch < 4; ch++) {
                asm volatile("bar.sync 3, 128;" ::: "memory");  // A buf free
#pragma unroll
                for (int q = 0; q < 8; q++) {
                    uint32_t off = (uint32_t)(r2 * 128 + (seg * 32 + q * 4) * 2);
                    split_store_f4(smem + SM_A, swz(off),
                                   *(const float4*)(arow + ch * 64 + q * 4),
                                   0, 8192);
                }
                asm volatile("bar.sync 3, 128;" ::: "memory");  // A buf ready

                const uint32_t bbase = sb + SM_B + (uint32_t)ch * 32768;
#pragma unroll
                for (int ks = 0; ks < 4; ks++) {
                    uint32_t aoff = swz((uint32_t)((pw * 16 + a_r) * 128
                                                   + (ks * 16 + a_c) * 2));
                    uint32_t ahi[4], alo[4];
                    ldmx4(ahi, sb + SM_A + aoff);
                    ldmx4(alo, sb + SM_A + 8192 + aoff);
#pragma unroll
                    for (int bt = 0; bt < 8; bt++) {
                        uint32_t boff = swz((uint32_t)((bt * 16 + b_nr) * 128
                                                       + (ks * 16 + b_kc) * 2));
                        uint32_t bhi[4], blo[4];
                        ldmx4(bhi, bbase + boff);
                        ldmx4(blo, bbase + 16384 + boff);
#pragma unroll
                        for (int sub = 0; sub < 2; sub++) {
                            float* a = acc[bt * 2 + sub];
                            mma16816(a, ahi, bhi[sub * 2], bhi[sub * 2 + 1]);
                            mma16816(a, ahi, blo[sub * 2], blo[sub * 2 + 1]);
                            mma16816(a, alo, bhi[sub * 2], bhi[sub * 2 + 1]);
                        }
                    }
                }
            }

            // epilogue: write 64x128 xp tile (+bias)
#pragma unroll
            for (int nt = 0; nt < 16; nt++) {
                int col = nt * 8 + tg * 2;
                float bx = bias[col], by = bias[col + 1];
                long r0 = mb + pw * 16 + g_;
                *(float2*)&g_xp[r0 * H_ + col] =
                    make_float2(acc[nt][0] + bx, acc[nt][1] + by);
                *(float2*)&g_xp[(r0 + 8) * H_ + col] =
                    make_float2(acc[nt][2] + bx, acc[nt][3] + by);
            }
            __threadfence_block();
            asm volatile("bar.sync 3, 128;" ::: "memory");
            if (wg == 0)
                ((volatile int*)(smem + SM_FLAGS))[row * 8 + ti] = 1;
        }
    }
}

// ---------------------------------------------------------------------------
// FC head: out = h_last @ W_fc^T + b_fc
// ---------------------------------------------------------------------------
__global__ void __launch_bounds__(256) fc_kernel(
    const float* __restrict__ Wfc,    // [O_, H_]
    const float* __restrict__ bfc,    // [O_]
    float* __restrict__ out)          // [B_, O_]
{
    __shared__ float Ws[64][129];
    __shared__ float Hs[32][128];

    const int tid = threadIdx.x;
    const int oc = blockIdx.x * 64;
    const int bc = blockIdx.y * 32;

    for (int idx = tid; idx < 64 * 128; idx += 256) {
        int rr = idx >> 7, cc = idx & 127;
        Ws[rr][cc] = (oc + rr < O_) ? Wfc[(oc + rr) * H_ + cc] : 0.f;
    }
    for (int idx = tid; idx < 32 * 128; idx += 256) {
        int rr = idx >> 7, cc = idx & 127;
        Hs[rr][cc] = g_h[(bc + rr) * H_ + cc];
    }
    __syncthreads();

    const int o_loc = tid & 63;
    const int bg    = tid >> 6;
    const int o     = oc + o_loc;
    const float bias = (o < O_) ? bfc[o] : 0.f;

    float accv[8];
#pragma unroll
    for (int bi = 0; bi < 8; bi++) accv[bi] = bias;

#pragma unroll 4
    for (int k = 0; k < H_; k++) {
        float wv = Ws[o_loc][k];
#pragma unroll
        for (int bi = 0; bi < 8; bi++)
            accv[bi] = fmaf(Hs[bg * 8 + bi][k], wv, accv[bi]);
    }

    if (o < O_) {
#pragma unroll
        for (int bi = 0; bi < 8; bi++)
            out[(long)(bc + bg * 8 + bi) * O_ + o] = accv[bi];
    }
}

// ---------------------------------------------------------------------------
// Launch
// ---------------------------------------------------------------------------
extern "C" void kernel_launch(void* const* d_in, const int* in_sizes, int n_in,
                              void* d_out, int out_size)
{
    const float* x    = (const float*)d_in[0];   // [256,512,256]
    const float* Wih  = (const float*)d_in[1];   // [128,256]
    const float* Whh  = (const float*)d_in[2];   // [128,128]
    const float* b_ih = (const float*)d_in[3];   // [128]
    const float* b_hh = (const float*)d_in[4];   // [128]
    const float* Wfc  = (const float*)d_in[5];   // [1000,128]
    const float* bfc  = (const float*)d_in[6];   // [1000]
    float* out = (float*)d_out;                  // [256,1000]

    cudaFuncSetAttribute(fused_rnn,
                         cudaFuncAttributeMaxDynamicSharedMemorySize, SM_TOTAL);

    fused_rnn<<<B_ / 2, 384, SM_TOTAL>>>(x, Wih, Whh, b_ih, b_hh);
    fc_kernel<<<dim3((O_ + 63) / 64, B_ / 32), 256>>>(Wfc, bfc, out);
}